// round 1
// baseline (speedup 1.0000x reference)
#include <cuda_runtime.h>
#include <math.h>

// Problem constants
#define BDIM   8
#define HW     4096
#define CDIM   256
#define NHEAD  8
#define HC     32
#define MROWS  (BDIM * HW)   // 32768
#define QKVN   768
#define KV_CH  8             // n-chunks for kv partial reduction

// Scratch (device globals; no allocations allowed)
__device__ float g_qkv[(size_t)MROWS * QKVN];            // ~100 MB
__device__ float g_ret[(size_t)MROWS * CDIM];            // ~33 MB
__device__ float g_hid[(size_t)MROWS * CDIM];            // ~33 MB
__device__ float g_kvp[(size_t)BDIM * NHEAD * KV_CH * HC * HC]; // 2 MB

// ---------------------------------------------------------------------------
// Packed fp32x2 FMA helpers (Blackwell sm_100+)
// ---------------------------------------------------------------------------
union F2 { float2 f; unsigned long long u; };

__device__ __forceinline__ unsigned long long pack_dup(float a) {
    unsigned long long r;
    unsigned ai = __float_as_uint(a);
    asm("mov.b64 %0, {%1, %1};" : "=l"(r) : "r"(ai));
    return r;
}

__device__ __forceinline__ void ffma2(unsigned long long& d,
                                      unsigned long long a,
                                      unsigned long long b) {
    asm("fma.rn.f32x2 %0, %1, %2, %0;" : "+l"(d) : "l"(a), "l"(b));
}

// ---------------------------------------------------------------------------
// SGEMM: C[M,N] = A[M,K] @ B[K,N] + bias[N]  (+ epilogue)
// EPI: 0 = +bias, 1 = gelu(+bias) exact erf, 2 = +bias + res
// BM=BN=128, BK=8, 256 threads, 8x8 per thread, packed f32x2 accumulators.
// Requires M%128==0, N%128==0, K%8==0 (true for all three calls).
// ---------------------------------------------------------------------------
template <int EPI>
__global__ __launch_bounds__(256) void sgemm_kernel(
    const float* __restrict__ A, const float* __restrict__ B,
    const float* __restrict__ bias, const float* __restrict__ res,
    float* __restrict__ C, int M, int N, int K)
{
    __shared__ float As[8][128];
    __shared__ float Bs[8][128];

    const int t  = threadIdx.x;
    const int m0 = blockIdx.y * 128;
    const int n0 = blockIdx.x * 128;
    const int ty = t >> 4;   // 0..15
    const int tx = t & 15;   // 0..15

    unsigned long long acc[8][4];
#pragma unroll
    for (int i = 0; i < 8; i++)
#pragma unroll
        for (int j = 0; j < 4; j++) acc[i][j] = 0ull;

    // Global load addressing
    const int ar = t >> 1;          // A tile row (0..127)
    const int ac = (t & 1) * 4;     // A tile col (0 or 4)
    const int br = t >> 5;          // B tile row (0..7)
    const int bc = (t & 31) * 4;    // B tile col (0..124)
    const float* Ag = A + (size_t)(m0 + ar) * K + ac;
    const float* Bg = B + (size_t)br * N + n0 + bc;

    for (int k0 = 0; k0 < K; k0 += 8) {
        float4 av = *(const float4*)(Ag + k0);
        float4 bv = *(const float4*)(Bg + (size_t)k0 * N);
        As[ac + 0][ar] = av.x;
        As[ac + 1][ar] = av.y;
        As[ac + 2][ar] = av.z;
        As[ac + 3][ar] = av.w;
        *(float4*)&Bs[br][bc] = bv;
        __syncthreads();

#pragma unroll
        for (int kk = 0; kk < 8; kk++) {
            float4 a0 = *(const float4*)&As[kk][ty * 8];
            float4 a1 = *(const float4*)&As[kk][ty * 8 + 4];
            float a[8] = {a0.x, a0.y, a0.z, a0.w, a1.x, a1.y, a1.z, a1.w};
            unsigned long long b[4];
            b[0] = *(const unsigned long long*)&Bs[kk][tx * 8 + 0];
            b[1] = *(const unsigned long long*)&Bs[kk][tx * 8 + 2];
            b[2] = *(const unsigned long long*)&Bs[kk][tx * 8 + 4];
            b[3] = *(const unsigned long long*)&Bs[kk][tx * 8 + 6];
#pragma unroll
            for (int i = 0; i < 8; i++) {
                unsigned long long aa = pack_dup(a[i]);
#pragma unroll
                for (int j = 0; j < 4; j++) ffma2(acc[i][j], aa, b[j]);
            }
        }
        __syncthreads();
    }

    // Epilogue
    const int nb = n0 + tx * 8;
#pragma unroll
    for (int i = 0; i < 8; i++) {
        const int m = m0 + ty * 8 + i;
        float o[8];
#pragma unroll
        for (int j = 0; j < 4; j++) {
            F2 v; v.u = acc[i][j];
            o[2 * j]     = v.f.x;
            o[2 * j + 1] = v.f.y;
        }
#pragma unroll
        for (int jj = 0; jj < 8; jj++) {
            float val = o[jj] + bias[nb + jj];
            if (EPI == 1) {
                val = 0.5f * val * (1.0f + erff(val * 0.7071067811865476f));
            }
            if (EPI == 2) {
                val += res[(size_t)m * N + nb + jj];
            }
            o[jj] = val;
        }
        *(float4*)&C[(size_t)m * N + nb]     = make_float4(o[0], o[1], o[2], o[3]);
        *(float4*)&C[(size_t)m * N + nb + 4] = make_float4(o[4], o[5], o[6], o[7]);
    }
}

// ---------------------------------------------------------------------------
// Stage 2a: per (b,h) LayerNorm(k), LayerNorm(v), partial kv = sum_n k^T v
// grid: (KV_CH, B*NHEAD), 256 threads (8 warps). Each warp keeps a full
// 32x32 accumulator in registers (32 regs/lane = column lane).
// ---------------------------------------------------------------------------
__global__ __launch_bounds__(256) void kv_partial_kernel(
    const float* __restrict__ kg, const float* __restrict__ kb,
    const float* __restrict__ vg, const float* __restrict__ vb)
{
    const int chunk = blockIdx.x;
    const int bh    = blockIdx.y;
    const int b = bh >> 3, h = bh & 7;
    const int t = threadIdx.x, w = t >> 5, lane = t & 31;

    const float gkl = kg[lane], bkl = kb[lane];
    const float gvl = vg[lane], bvl = vb[lane];

    float acc[32];
#pragma unroll
    for (int i = 0; i < 32; i++) acc[i] = 0.0f;

    const int nbase = chunk * (HW / KV_CH);   // 512 rows per chunk
    for (int n = nbase + w; n < nbase + HW / KV_CH; n += 8) {
        const float* row = g_qkv + (size_t)(b * HW + n) * QKVN + h * 96;
        float kx = row[32 + lane];
        float vx = row[64 + lane];

        // LayerNorm k (population variance over 32)
        float s = kx;
#pragma unroll
        for (int off = 16; off > 0; off >>= 1) s += __shfl_xor_sync(0xffffffffu, s, off);
        float mu = s * (1.0f / 32.0f);
        float d  = kx - mu;
        float s2 = d * d;
#pragma unroll
        for (int off = 16; off > 0; off >>= 1) s2 += __shfl_xor_sync(0xffffffffu, s2, off);
        float kn = d * rsqrtf(s2 * (1.0f / 32.0f) + 1e-5f) * gkl + bkl;

        // LayerNorm v
        float sv = vx;
#pragma unroll
        for (int off = 16; off > 0; off >>= 1) sv += __shfl_xor_sync(0xffffffffu, sv, off);
        float muv = sv * (1.0f / 32.0f);
        float dv  = vx - muv;
        float sv2 = dv * dv;
#pragma unroll
        for (int off = 16; off > 0; off >>= 1) sv2 += __shfl_xor_sync(0xffffffffu, sv2, off);
        float vn = dv * rsqrtf(sv2 * (1.0f / 32.0f) + 1e-5f) * gvl + bvl;

        // Outer product: acc[i][lane] += kn_i * vn_lane
#pragma unroll
        for (int i = 0; i < 32; i++)
            acc[i] += __shfl_sync(0xffffffffu, kn, i) * vn;
    }

    __shared__ float buf[8][32][32];
#pragma unroll
    for (int i = 0; i < 32; i++) buf[w][i][lane] = acc[i];
    __syncthreads();

    float* outp = g_kvp + ((size_t)bh * KV_CH + chunk) * (HC * HC);
    for (int idx = t; idx < HC * HC; idx += 256) {
        float s = 0.0f;
#pragma unroll
        for (int ww = 0; ww < 8; ww++) s += buf[ww][idx >> 5][idx & 31];
        outp[idx] = s * (1.0f / (float)HW);
    }
}

// ---------------------------------------------------------------------------
// Stage 2c: out[n,:] = q[n,:] @ kv (32x32), + residual x -> g_ret
// grid: (16, B*NHEAD), 256 threads (one row per thread, 256 rows per block)
// ---------------------------------------------------------------------------
__global__ __launch_bounds__(256) void attn_out_kernel(const float* __restrict__ x)
{
    const int chunk = blockIdx.x;  // 0..15, 256 rows each
    const int bh    = blockIdx.y;
    const int b = bh >> 3, h = bh & 7;
    const int t = threadIdx.x;

    __shared__ float kv[HC][HC];
    for (int idx = t; idx < HC * HC; idx += 256) {
        float s = 0.0f;
#pragma unroll
        for (int c = 0; c < KV_CH; c++)
            s += g_kvp[((size_t)bh * KV_CH + c) * (HC * HC) + idx];
        kv[idx >> 5][idx & 31] = s;
    }
    __syncthreads();

    const int n = chunk * 256 + t;
    const size_t rowg = (size_t)(b * HW + n);
    const float* q = g_qkv + rowg * QKVN + h * 96;

    float qv[32];
#pragma unroll
    for (int i = 0; i < 32; i += 4) {
        float4 v = *(const float4*)(q + i);
        qv[i] = v.x; qv[i + 1] = v.y; qv[i + 2] = v.z; qv[i + 3] = v.w;
    }

    float acc[32];
#pragma unroll
    for (int j = 0; j < 32; j++) acc[j] = 0.0f;
#pragma unroll
    for (int i = 0; i < 32; i++) {
        float qi = qv[i];
#pragma unroll
        for (int j = 0; j < 32; j++) acc[j] += qi * kv[i][j];
    }

    const float* xr = x + rowg * CDIM + h * HC;
    float* rr = g_ret + rowg * CDIM + h * HC;
#pragma unroll
    for (int j = 0; j < 32; j += 4) {
        float4 xv = *(const float4*)(xr + j);
        float4 o;
        o.x = acc[j]     + xv.x;
        o.y = acc[j + 1] + xv.y;
        o.z = acc[j + 2] + xv.z;
        o.w = acc[j + 3] + xv.w;
        *(float4*)(rr + j) = o;
    }
}

// ---------------------------------------------------------------------------
// Launch
// ---------------------------------------------------------------------------
extern "C" void kernel_launch(void* const* d_in, const int* in_sizes, int n_in,
                              void* d_out, int out_size)
{
    const float* x     = (const float*)d_in[0];
    const float* w_qkv = (const float*)d_in[1];
    const float* b_qkv = (const float*)d_in[2];
    const float* kln_g = (const float*)d_in[3];
    const float* kln_b = (const float*)d_in[4];
    const float* vln_g = (const float*)d_in[5];
    const float* vln_b = (const float*)d_in[6];
    const float* w1    = (const float*)d_in[7];
    const float* b1    = (const float*)d_in[8];
    const float* w2    = (const float*)d_in[9];
    const float* b2    = (const float*)d_in[10];
    float* out = (float*)d_out;

    void *p_qkv = nullptr, *p_ret = nullptr, *p_hid = nullptr;
    cudaGetSymbolAddress(&p_qkv, g_qkv);
    cudaGetSymbolAddress(&p_ret, g_ret);
    cudaGetSymbolAddress(&p_hid, g_hid);

    dim3 blk(256);

    // 1) qkv = x @ w_qkv + b_qkv      [32768, 768]
    sgemm_kernel<0><<<dim3(QKVN / 128, MROWS / 128), blk>>>(
        x, w_qkv, b_qkv, nullptr, (float*)p_qkv, MROWS, QKVN, CDIM);

    // 2) LN(k), LN(v), kv partials; then out = q @ kv + x -> g_ret
    kv_partial_kernel<<<dim3(KV_CH, BDIM * NHEAD), blk>>>(kln_g, kln_b, vln_g, vln_b);
    attn_out_kernel<<<dim3(16, BDIM * NHEAD), blk>>>(x);

    // 3) hid = gelu(ret @ w1 + b1)
    sgemm_kernel<1><<<dim3(CDIM / 128, MROWS / 128), blk>>>(
        (const float*)p_ret, w1, b1, nullptr, (float*)p_hid, MROWS, CDIM, CDIM);

    // 4) out = hid @ w2 + b2 + x
    sgemm_kernel<2><<<dim3(CDIM / 128, MROWS / 128), blk>>>(
        (const float*)p_hid, w2, b2, x, out, MROWS, CDIM, CDIM);
}

// round 3
// speedup vs baseline: 1.4222x; 1.4222x over previous
#include <cuda_runtime.h>
#include <cuda_bf16.h>
#include <math.h>
#include <stdint.h>

// Problem constants
#define BDIM   8
#define HW     4096
#define CDIM   256
#define NHEAD  8
#define HC     32
#define MROWS  (BDIM * HW)   // 32768
#define QKVN   768
#define KV_CH  8

// ---------------------------------------------------------------------------
// Scratch (device globals)
// ---------------------------------------------------------------------------
__device__ float          g_qkv[(size_t)MROWS * QKVN];
__device__ __nv_bfloat16  g_xh[(size_t)MROWS * CDIM];
__device__ __nv_bfloat16  g_xl[(size_t)MROWS * CDIM];
__device__ __nv_bfloat16  g_reth[(size_t)MROWS * CDIM];
__device__ __nv_bfloat16  g_retl[(size_t)MROWS * CDIM];
__device__ __nv_bfloat16  g_hidh[(size_t)MROWS * CDIM];
__device__ __nv_bfloat16  g_hidl[(size_t)MROWS * CDIM];
__device__ __nv_bfloat16  g_wqh[(size_t)QKVN * CDIM];    // [N,K]
__device__ __nv_bfloat16  g_wql[(size_t)QKVN * CDIM];
__device__ __nv_bfloat16  g_w1h[CDIM * CDIM];
__device__ __nv_bfloat16  g_w1l[CDIM * CDIM];
__device__ __nv_bfloat16  g_w2h[CDIM * CDIM];
__device__ __nv_bfloat16  g_w2l[CDIM * CDIM];
__device__ float          g_kvp[BDIM * NHEAD * KV_CH * HC * HC];

// ---------------------------------------------------------------------------
// PTX helpers (sm_80-era: valid under compute_103)
// ---------------------------------------------------------------------------
__device__ __forceinline__ uint32_t smem_u32(const void* p) {
    uint32_t a;
    asm("{ .reg .u64 t; cvta.to.shared.u64 t, %1; cvt.u32.u64 %0, t; }"
        : "=r"(a) : "l"(p));
    return a;
}

__device__ __forceinline__ void cp_async16(uint32_t dst, const void* src) {
    asm volatile("cp.async.cg.shared.global [%0], [%1], 16;"
                 :: "r"(dst), "l"(src) : "memory");
}
__device__ __forceinline__ void cp_commit() {
    asm volatile("cp.async.commit_group;" ::: "memory");
}
template <int N>
__device__ __forceinline__ void cp_wait() {
    asm volatile("cp.async.wait_group %0;" :: "n"(N) : "memory");
}

__device__ __forceinline__ void ldm4(uint32_t* r, uint32_t addr) {
    asm volatile("ldmatrix.sync.aligned.m8n8.x4.shared.b16 {%0,%1,%2,%3}, [%4];"
                 : "=r"(r[0]), "=r"(r[1]), "=r"(r[2]), "=r"(r[3]) : "r"(addr));
}

__device__ __forceinline__ void mma_bf16(float* d, const uint32_t* a, const uint32_t* b) {
    asm volatile(
        "mma.sync.aligned.m16n8k16.row.col.f32.bf16.bf16.f32 "
        "{%0,%1,%2,%3}, {%4,%5,%6,%7}, {%8,%9}, {%0,%1,%2,%3};"
        : "+f"(d[0]), "+f"(d[1]), "+f"(d[2]), "+f"(d[3])
        : "r"(a[0]), "r"(a[1]), "r"(a[2]), "r"(a[3]), "r"(b[0]), "r"(b[1]));
}

__device__ __forceinline__ void split_bf16(float v, __nv_bfloat16& h, __nv_bfloat16& l) {
    h = __float2bfloat16(v);
    l = __float2bfloat16(v - __bfloat162float(h));
}

// ---------------------------------------------------------------------------
// Tensor-core GEMM via mma.sync (HMMA):
//   C[M,N] = A[M,256] @ B[N,256]^T, 3-pass bf16 split, fp32 accum.
// Tile 128x128, BK=32, 256 threads, warp grid 2(m) x 4(n), warp tile 64x32.
// EPI 0: C=D+bias (fp32, ldc)   EPI 1: gelu(D+bias)->Ch/Cl bf16
// EPI 2: C=D+bias+res (fp32)
// ---------------------------------------------------------------------------
#define SSTR 40          // smem row stride in bf16 elems (80B, ldmatrix conflict-free)
#define TILEB (128 * SSTR)

template <int EPI>
__global__ __launch_bounds__(256) void tc_gemm(
    const __nv_bfloat16* __restrict__ Ah, const __nv_bfloat16* __restrict__ Al,
    const __nv_bfloat16* __restrict__ Bh, const __nv_bfloat16* __restrict__ Bl,
    const float* __restrict__ bias, const float* __restrict__ res,
    float* __restrict__ C,
    __nv_bfloat16* __restrict__ Ch, __nv_bfloat16* __restrict__ Cl,
    int ldc)
{
    __shared__ __align__(128) __nv_bfloat16 sA[2][TILEB];
    __shared__ __align__(128) __nv_bfloat16 sB[2][TILEB];

    const int t    = threadIdx.x;
    const int lane = t & 31;
    const int wid  = t >> 5;
    const int wm   = wid & 1;      // 0..1
    const int wn   = wid >> 1;     // 0..3
    const int m0   = blockIdx.x * 128;
    const int n0   = blockIdx.y * 128;

    const uint32_t sAu = smem_u32(sA);
    const uint32_t sBu = smem_u32(sB);

    const __nv_bfloat16* APS[3] = {Ah, Ah, Al};
    const __nv_bfloat16* BPS[3] = {Bh, Bl, Bh};

    // global->smem: 4 threads per 64B row, 2 rows per thread
    const int lrow = t >> 2;         // 0..63
    const int lcol = (t & 3) * 8;    // elem offset (16B)

    float acc[4][4][4];
#pragma unroll
    for (int i = 0; i < 4; i++)
#pragma unroll
        for (int j = 0; j < 4; j++)
#pragma unroll
            for (int q = 0; q < 4; q++) acc[i][j][q] = 0.0f;

    const int S = 24;  // 3 passes * 8 k-chunks

    // issue stage s into buffer buf
    auto issue = [&](int s, int buf) {
        const int pass = s >> 3;
        const int k0   = (s & 7) * 32;
        const __nv_bfloat16* Ap = APS[pass];
        const __nv_bfloat16* Bp = BPS[pass];
#pragma unroll
        for (int i = 0; i < 2; i++) {
            const int row = lrow + i * 64;
            const uint32_t so = (uint32_t)(buf * TILEB + row * SSTR + lcol) * 2;
            cp_async16(sAu + so, Ap + (size_t)(m0 + row) * CDIM + k0 + lcol);
            cp_async16(sBu + so, Bp + (size_t)(n0 + row) * CDIM + k0 + lcol);
        }
        cp_commit();
    };

    auto compute = [&](int buf) {
        const uint32_t ab = sAu + (uint32_t)buf * TILEB * 2;
        const uint32_t bb = sBu + (uint32_t)buf * TILEB * 2;
        const int rsel  = lane & 15;
        const int khalf = (lane >> 4) * 8;
#pragma unroll
        for (int ks = 0; ks < 2; ks++) {
            uint32_t a[4][4];
#pragma unroll
            for (int im = 0; im < 4; im++) {
                const int r = wm * 64 + im * 16 + rsel;
                ldm4(a[im], ab + (uint32_t)(r * SSTR + ks * 16 + khalf) * 2);
            }
            uint32_t b[4][2];
#pragma unroll
            for (int ib = 0; ib < 2; ib++) {
                const int r = wn * 32 + ib * 16 + rsel;
                uint32_t q[4];
                ldm4(q, bb + (uint32_t)(r * SSTR + ks * 16 + khalf) * 2);
                b[ib * 2 + 0][0] = q[0]; b[ib * 2 + 0][1] = q[2];
                b[ib * 2 + 1][0] = q[1]; b[ib * 2 + 1][1] = q[3];
            }
#pragma unroll
            for (int im = 0; im < 4; im++)
#pragma unroll
                for (int jn = 0; jn < 4; jn++)
                    mma_bf16(acc[im][jn], a[im], b[jn]);
        }
    };

    issue(0, 0);
    for (int s = 0; s < S; s++) {
        if (s + 1 < S) {
            issue(s + 1, (s + 1) & 1);
            cp_wait<1>();
        } else {
            cp_wait<0>();
        }
        __syncthreads();
        compute(s & 1);
        __syncthreads();
    }

    // Epilogue
    const int cbase = n0 + wn * 32 + (lane & 3) * 2;
#pragma unroll
    for (int im = 0; im < 4; im++) {
        const int rbase = m0 + wm * 64 + im * 16 + (lane >> 2);
#pragma unroll
        for (int half = 0; half < 2; half++) {
            const int row = rbase + half * 8;
#pragma unroll
            for (int jn = 0; jn < 4; jn++) {
                const int col = cbase + jn * 8;
                float v0 = acc[im][jn][half * 2 + 0] + bias[col];
                float v1 = acc[im][jn][half * 2 + 1] + bias[col + 1];
                if (EPI == 0) {
                    float2 o = make_float2(v0, v1);
                    *(float2*)(C + (size_t)row * ldc + col) = o;
                } else if (EPI == 1) {
                    v0 = 0.5f * v0 * (1.0f + erff(v0 * 0.7071067811865476f));
                    v1 = 0.5f * v1 * (1.0f + erff(v1 * 0.7071067811865476f));
                    __nv_bfloat16 h0, l0, h1, l1;
                    split_bf16(v0, h0, l0);
                    split_bf16(v1, h1, l1);
                    __nv_bfloat162 hp; hp.x = h0; hp.y = h1;
                    __nv_bfloat162 lp; lp.x = l0; lp.y = l1;
                    *(__nv_bfloat162*)(Ch + (size_t)row * ldc + col) = hp;
                    *(__nv_bfloat162*)(Cl + (size_t)row * ldc + col) = lp;
                } else {
                    float2 rv = *(const float2*)(res + (size_t)row * ldc + col);
                    float2 o = make_float2(v0 + rv.x, v1 + rv.y);
                    *(float2*)(C + (size_t)row * ldc + col) = o;
                }
            }
        }
    }
}

// ---------------------------------------------------------------------------
// Split fp32 -> bf16 hi/lo
// ---------------------------------------------------------------------------
__global__ __launch_bounds__(256) void split_kernel(
    const float* __restrict__ in, __nv_bfloat16* __restrict__ hi,
    __nv_bfloat16* __restrict__ lo, int n)
{
    int i = (blockIdx.x * 256 + threadIdx.x) * 4;
    if (i >= n) return;
    float4 v = *(const float4*)(in + i);
    __nv_bfloat16 h0, l0, h1, l1, h2, l2, h3, l3;
    split_bf16(v.x, h0, l0);
    split_bf16(v.y, h1, l1);
    split_bf16(v.z, h2, l2);
    split_bf16(v.w, h3, l3);
    __nv_bfloat162 hp0; hp0.x = h0; hp0.y = h1;
    __nv_bfloat162 hp1; hp1.x = h2; hp1.y = h3;
    __nv_bfloat162 lp0; lp0.x = l0; lp0.y = l1;
    __nv_bfloat162 lp1; lp1.x = l2; lp1.y = l3;
    *(__nv_bfloat162*)(hi + i)     = hp0;
    *(__nv_bfloat162*)(hi + i + 2) = hp1;
    *(__nv_bfloat162*)(lo + i)     = lp0;
    *(__nv_bfloat162*)(lo + i + 2) = lp1;
}

// Weight transpose + split: w [K,N] fp32 -> [N,K] bf16 hi/lo
__global__ __launch_bounds__(256) void wsplit_kernel(
    const float* __restrict__ w, __nv_bfloat16* __restrict__ hi,
    __nv_bfloat16* __restrict__ lo, int K, int N)
{
    int idx = blockIdx.x * 256 + threadIdx.x;
    if (idx >= K * N) return;
    int nn = idx / K;
    int kk = idx - nn * K;
    float v = w[(size_t)kk * N + nn];
    __nv_bfloat16 h, l;
    split_bf16(v, h, l);
    hi[idx] = h;
    lo[idx] = l;
}

// ---------------------------------------------------------------------------
// Attention stage (SIMT)
// ---------------------------------------------------------------------------
__global__ __launch_bounds__(256) void kv_partial_kernel(
    const float* __restrict__ kg, const float* __restrict__ kb,
    const float* __restrict__ vg, const float* __restrict__ vb)
{
    const int chunk = blockIdx.x;
    const int bh    = blockIdx.y;
    const int b = bh >> 3, h = bh & 7;
    const int t = threadIdx.x, w = t >> 5, lane = t & 31;

    const float gkl = kg[lane], bkl = kb[lane];
    const float gvl = vg[lane], bvl = vb[lane];

    float acc[32];
#pragma unroll
    for (int i = 0; i < 32; i++) acc[i] = 0.0f;

    const int nbase = chunk * (HW / KV_CH);
    for (int n = nbase + w; n < nbase + HW / KV_CH; n += 8) {
        const float* row = g_qkv + (size_t)(b * HW + n) * QKVN + h * 96;
        float kx = row[32 + lane];
        float vx = row[64 + lane];

        float s = kx;
#pragma unroll
        for (int off = 16; off > 0; off >>= 1) s += __shfl_xor_sync(0xffffffffu, s, off);
        float mu = s * (1.0f / 32.0f);
        float d  = kx - mu;
        float s2 = d * d;
#pragma unroll
        for (int off = 16; off > 0; off >>= 1) s2 += __shfl_xor_sync(0xffffffffu, s2, off);
        float kn = d * rsqrtf(s2 * (1.0f / 32.0f) + 1e-5f) * gkl + bkl;

        float sv = vx;
#pragma unroll
        for (int off = 16; off > 0; off >>= 1) sv += __shfl_xor_sync(0xffffffffu, sv, off);
        float muv = sv * (1.0f / 32.0f);
        float dv  = vx - muv;
        float sv2 = dv * dv;
#pragma unroll
        for (int off = 16; off > 0; off >>= 1) sv2 += __shfl_xor_sync(0xffffffffu, sv2, off);
        float vn = dv * rsqrtf(sv2 * (1.0f / 32.0f) + 1e-5f) * gvl + bvl;

#pragma unroll
        for (int i = 0; i < 32; i++)
            acc[i] += __shfl_sync(0xffffffffu, kn, i) * vn;
    }

    __shared__ float buf[8][32][32];
#pragma unroll
    for (int i = 0; i < 32; i++) buf[w][i][lane] = acc[i];
    __syncthreads();

    float* outp = g_kvp + ((size_t)bh * KV_CH + chunk) * (HC * HC);
    for (int idx = t; idx < HC * HC; idx += 256) {
        float s = 0.0f;
#pragma unroll
        for (int ww = 0; ww < 8; ww++) s += buf[ww][idx >> 5][idx & 31];
        outp[idx] = s * (1.0f / (float)HW);
    }
}

__global__ __launch_bounds__(256) void attn_out_kernel(const float* __restrict__ x)
{
    const int chunk = blockIdx.x;
    const int bh    = blockIdx.y;
    const int b = bh >> 3, h = bh & 7;
    const int t = threadIdx.x;

    __shared__ float kv[HC][HC];
    for (int idx = t; idx < HC * HC; idx += 256) {
        float s = 0.0f;
#pragma unroll
        for (int c = 0; c < KV_CH; c++)
            s += g_kvp[((size_t)bh * KV_CH + c) * (HC * HC) + idx];
        kv[idx >> 5][idx & 31] = s;
    }
    __syncthreads();

    const int n = chunk * 256 + t;
    const size_t rowg = (size_t)(b * HW + n);
    const float* q = g_qkv + rowg * QKVN + h * 96;

    float qv[32];
#pragma unroll
    for (int i = 0; i < 32; i += 4) {
        float4 v = *(const float4*)(q + i);
        qv[i] = v.x; qv[i + 1] = v.y; qv[i + 2] = v.z; qv[i + 3] = v.w;
    }

    float acc[32];
#pragma unroll
    for (int j = 0; j < 32; j++) acc[j] = 0.0f;
#pragma unroll
    for (int i = 0; i < 32; i++) {
        float qi = qv[i];
#pragma unroll
        for (int j = 0; j < 32; j++) acc[j] += qi * kv[i][j];
    }

    const float* xr = x + rowg * CDIM + h * HC;
    __nv_bfloat16* hr = g_reth + rowg * CDIM + h * HC;
    __nv_bfloat16* lr = g_retl + rowg * CDIM + h * HC;
#pragma unroll
    for (int j = 0; j < 32; j += 4) {
        float4 xv = *(const float4*)(xr + j);
        float v0 = acc[j]     + xv.x;
        float v1 = acc[j + 1] + xv.y;
        float v2 = acc[j + 2] + xv.z;
        float v3 = acc[j + 3] + xv.w;
        __nv_bfloat16 h0, l0, h1, l1, h2, l2, h3, l3;
        split_bf16(v0, h0, l0);
        split_bf16(v1, h1, l1);
        split_bf16(v2, h2, l2);
        split_bf16(v3, h3, l3);
        __nv_bfloat162 hp0; hp0.x = h0; hp0.y = h1;
        __nv_bfloat162 hp1; hp1.x = h2; hp1.y = h3;
        __nv_bfloat162 lp0; lp0.x = l0; lp0.y = l1;
        __nv_bfloat162 lp1; lp1.x = l2; lp1.y = l3;
        *(__nv_bfloat162*)(hr + j)     = hp0;
        *(__nv_bfloat162*)(hr + j + 2) = hp1;
        *(__nv_bfloat162*)(lr + j)     = lp0;
        *(__nv_bfloat162*)(lr + j + 2) = lp1;
    }
}

// ---------------------------------------------------------------------------
// Launch
// ---------------------------------------------------------------------------
extern "C" void kernel_launch(void* const* d_in, const int* in_sizes, int n_in,
                              void* d_out, int out_size)
{
    const float* x     = (const float*)d_in[0];
    const float* w_qkv = (const float*)d_in[1];
    const float* b_qkv = (const float*)d_in[2];
    const float* kln_g = (const float*)d_in[3];
    const float* kln_b = (const float*)d_in[4];
    const float* vln_g = (const float*)d_in[5];
    const float* vln_b = (const float*)d_in[6];
    const float* w1    = (const float*)d_in[7];
    const float* b1    = (const float*)d_in[8];
    const float* w2    = (const float*)d_in[9];
    const float* b2    = (const float*)d_in[10];
    float* out = (float*)d_out;

    void *p_qkv, *p_xh, *p_xl, *p_reth, *p_retl, *p_hidh, *p_hidl;
    void *p_wqh, *p_wql, *p_w1h, *p_w1l, *p_w2h, *p_w2l;
    cudaGetSymbolAddress(&p_qkv, g_qkv);
    cudaGetSymbolAddress(&p_xh, g_xh);
    cudaGetSymbolAddress(&p_xl, g_xl);
    cudaGetSymbolAddress(&p_reth, g_reth);
    cudaGetSymbolAddress(&p_retl, g_retl);
    cudaGetSymbolAddress(&p_hidh, g_hidh);
    cudaGetSymbolAddress(&p_hidl, g_hidl);
    cudaGetSymbolAddress(&p_wqh, g_wqh);
    cudaGetSymbolAddress(&p_wql, g_wql);
    cudaGetSymbolAddress(&p_w1h, g_w1h);
    cudaGetSymbolAddress(&p_w1l, g_w1l);
    cudaGetSymbolAddress(&p_w2h, g_w2h);
    cudaGetSymbolAddress(&p_w2l, g_w2l);

    const int nx = MROWS * CDIM;

    split_kernel<<<(nx / 4 + 255) / 256, 256>>>(
        x, (__nv_bfloat16*)p_xh, (__nv_bfloat16*)p_xl, nx);
    wsplit_kernel<<<(CDIM * QKVN + 255) / 256, 256>>>(
        w_qkv, (__nv_bfloat16*)p_wqh, (__nv_bfloat16*)p_wql, CDIM, QKVN);
    wsplit_kernel<<<(CDIM * CDIM + 255) / 256, 256>>>(
        w1, (__nv_bfloat16*)p_w1h, (__nv_bfloat16*)p_w1l, CDIM, CDIM);
    wsplit_kernel<<<(CDIM * CDIM + 255) / 256, 256>>>(
        w2, (__nv_bfloat16*)p_w2h, (__nv_bfloat16*)p_w2l, CDIM, CDIM);

    // 1) qkv = x @ w_qkv + b_qkv  [32768, 768] fp32
    tc_gemm<0><<<dim3(MROWS / 128, QKVN / 128), 256>>>(
        (const __nv_bfloat16*)p_xh, (const __nv_bfloat16*)p_xl,
        (const __nv_bfloat16*)p_wqh, (const __nv_bfloat16*)p_wql,
        b_qkv, nullptr, (float*)p_qkv, nullptr, nullptr, QKVN);

    // 2) attention
    kv_partial_kernel<<<dim3(KV_CH, BDIM * NHEAD), 256>>>(kln_g, kln_b, vln_g, vln_b);
    attn_out_kernel<<<dim3(16, BDIM * NHEAD), 256>>>(x);

    // 3) hid = gelu(ret @ w1 + b1) -> bf16 split
    tc_gemm<1><<<dim3(MROWS / 128, CDIM / 128), 256>>>(
        (const __nv_bfloat16*)p_reth, (const __nv_bfloat16*)p_retl,
        (const __nv_bfloat16*)p_w1h, (const __nv_bfloat16*)p_w1l,
        b1, nullptr, nullptr, (__nv_bfloat16*)p_hidh, (__nv_bfloat16*)p_hidl, CDIM);

    // 4) out = hid @ w2 + b2 + x
    tc_gemm<2><<<dim3(MROWS / 128, CDIM / 128), 256>>>(
        (const __nv_bfloat16*)p_hidh, (const __nv_bfloat16*)p_hidl,
        (const __nv_bfloat16*)p_w2h, (const __nv_bfloat16*)p_w2l,
        b2, x, out, nullptr, nullptr, CDIM);
}

// round 4
// speedup vs baseline: 1.5889x; 1.1172x over previous
#include <cuda_runtime.h>
#include <cuda_bf16.h>
#include <math.h>
#include <stdint.h>

// Problem constants
#define BDIM   8
#define HW     4096
#define CDIM   256
#define NHEAD  8
#define HC     32
#define MROWS  (BDIM * HW)   // 32768
#define QKVN   768
#define KV_CH  8

// ---------------------------------------------------------------------------
// Scratch (device globals)
// ---------------------------------------------------------------------------
__device__ float          g_qkv[(size_t)MROWS * QKVN];
__device__ __nv_bfloat16  g_xh[(size_t)MROWS * CDIM];
__device__ __nv_bfloat16  g_xl[(size_t)MROWS * CDIM];
__device__ __nv_bfloat16  g_reth[(size_t)MROWS * CDIM];
__device__ __nv_bfloat16  g_retl[(size_t)MROWS * CDIM];
__device__ __nv_bfloat16  g_hidh[(size_t)MROWS * CDIM];
__device__ __nv_bfloat16  g_hidl[(size_t)MROWS * CDIM];
__device__ __nv_bfloat16  g_wqh[(size_t)QKVN * CDIM];    // [N,K]
__device__ __nv_bfloat16  g_wql[(size_t)QKVN * CDIM];
__device__ __nv_bfloat16  g_w1h[CDIM * CDIM];
__device__ __nv_bfloat16  g_w1l[CDIM * CDIM];
__device__ __nv_bfloat16  g_w2h[CDIM * CDIM];
__device__ __nv_bfloat16  g_w2l[CDIM * CDIM];
__device__ float          g_kvp[BDIM * NHEAD * KV_CH * HC * HC];

// ---------------------------------------------------------------------------
// PTX helpers (sm_80-era: valid under compute_103)
// ---------------------------------------------------------------------------
__device__ __forceinline__ uint32_t smem_u32(const void* p) {
    uint32_t a;
    asm("{ .reg .u64 t; cvta.to.shared.u64 t, %1; cvt.u32.u64 %0, t; }"
        : "=r"(a) : "l"(p));
    return a;
}

__device__ __forceinline__ void cp_async16(uint32_t dst, const void* src) {
    asm volatile("cp.async.cg.shared.global [%0], [%1], 16;"
                 :: "r"(dst), "l"(src) : "memory");
}
__device__ __forceinline__ void cp_commit() {
    asm volatile("cp.async.commit_group;" ::: "memory");
}
template <int N>
__device__ __forceinline__ void cp_wait() {
    asm volatile("cp.async.wait_group %0;" :: "n"(N) : "memory");
}

__device__ __forceinline__ void ldm4(uint32_t* r, uint32_t addr) {
    asm volatile("ldmatrix.sync.aligned.m8n8.x4.shared.b16 {%0,%1,%2,%3}, [%4];"
                 : "=r"(r[0]), "=r"(r[1]), "=r"(r[2]), "=r"(r[3]) : "r"(addr));
}

__device__ __forceinline__ void mma_bf16(float* d, const uint32_t* a, const uint32_t* b) {
    asm volatile(
        "mma.sync.aligned.m16n8k16.row.col.f32.bf16.bf16.f32 "
        "{%0,%1,%2,%3}, {%4,%5,%6,%7}, {%8,%9}, {%0,%1,%2,%3};"
        : "+f"(d[0]), "+f"(d[1]), "+f"(d[2]), "+f"(d[3])
        : "r"(a[0]), "r"(a[1]), "r"(a[2]), "r"(a[3]), "r"(b[0]), "r"(b[1]));
}

__device__ __forceinline__ void split_bf16(float v, __nv_bfloat16& h, __nv_bfloat16& l) {
    h = __float2bfloat16(v);
    l = __float2bfloat16(v - __bfloat162float(h));
}

// ---------------------------------------------------------------------------
// Merged-pass split GEMM via mma.sync:
//   C[M,N] = A[M,256] @ B[N,256]^T, D = Ah*Bh + Ah*Bl + Al*Bh, fp32 accum.
// Per k-chunk (BK=32): load Ah/Al/Bh/Bl tiles once, issue all 3 MMA groups.
// Tile 128x128, 256 threads, warp grid 2(m) x 4(n), warp tile 64x32.
// Dynamic smem: 4 tiles x 2 buffers x 10240B = 80 KB.
// EPI 0: C=D+bias (fp32)  EPI 1: gelu(D+bias)->Ch/Cl bf16  EPI 2: C=D+bias+res
// ---------------------------------------------------------------------------
#define SSTR 40                // smem row stride in bf16 elems (80B)
#define TILEE (128 * SSTR)     // elems per tile
#define TILEBYT (TILEE * 2)    // 10240 bytes
#define SMEM_TOTAL (TILEBYT * 8)  // 81920

template <int EPI>
__global__ __launch_bounds__(256, 2) void tc_gemm(
    const __nv_bfloat16* __restrict__ Ah, const __nv_bfloat16* __restrict__ Al,
    const __nv_bfloat16* __restrict__ Bh, const __nv_bfloat16* __restrict__ Bl,
    const float* __restrict__ bias, const float* __restrict__ res,
    float* __restrict__ C,
    __nv_bfloat16* __restrict__ Ch, __nv_bfloat16* __restrict__ Cl,
    int ldc)
{
    extern __shared__ __align__(128) unsigned char smraw[];

    const int t    = threadIdx.x;
    const int lane = t & 31;
    const int wid  = t >> 5;
    const int wm   = wid & 1;      // 0..1
    const int wn   = wid >> 1;     // 0..3
    const int m0   = blockIdx.x * 128;
    const int n0   = blockIdx.y * 128;

    const uint32_t sb = smem_u32(smraw);

    // global->smem mapping: 4 threads per 64B row, 2 rows per thread per tile
    const int lrow = t >> 2;         // 0..63
    const int lcol = (t & 3) * 8;    // elem offset (16B chunks)

    float acc[4][4][4];
#pragma unroll
    for (int i = 0; i < 4; i++)
#pragma unroll
        for (int j = 0; j < 4; j++)
#pragma unroll
            for (int q = 0; q < 4; q++) acc[i][j][q] = 0.0f;

    const __nv_bfloat16* tsrc[4] = {Ah, Al, Bh, Bl};
    const int tbase[4] = {m0, m0, n0, n0};

    auto issue = [&](int s, int buf) {
        const int k0 = s * 32;
#pragma unroll
        for (int tile = 0; tile < 4; tile++) {
            const __nv_bfloat16* src = tsrc[tile] + (size_t)(tbase[tile] + lrow) * CDIM + k0 + lcol;
            const uint32_t dbase = sb + (uint32_t)(buf * 4 + tile) * TILEBYT
                                 + (uint32_t)(lrow * SSTR + lcol) * 2;
#pragma unroll
            for (int i = 0; i < 2; i++) {
                cp_async16(dbase + i * 64 * SSTR * 2, src + (size_t)i * 64 * CDIM);
            }
        }
        cp_commit();
    };

    auto compute = [&](int buf) {
        const uint32_t ah = sb + (uint32_t)(buf * 4 + 0) * TILEBYT;
        const uint32_t al = sb + (uint32_t)(buf * 4 + 1) * TILEBYT;
        const uint32_t bh = sb + (uint32_t)(buf * 4 + 2) * TILEBYT;
        const uint32_t bl = sb + (uint32_t)(buf * 4 + 3) * TILEBYT;
        const int rsel  = lane & 15;
        const int khalf = (lane >> 4) * 8;
#pragma unroll
        for (int ks = 0; ks < 2; ks++) {
            const uint32_t koff = (uint32_t)(ks * 16 + khalf) * 2;

            uint32_t a[4][4];
#pragma unroll
            for (int im = 0; im < 4; im++) {
                const int r = wm * 64 + im * 16 + rsel;
                ldm4(a[im], ah + (uint32_t)(r * SSTR) * 2 + koff);
            }
            uint32_t bhf[4][2], blf[4][2];
#pragma unroll
            for (int ib = 0; ib < 2; ib++) {
                const int r = wn * 32 + ib * 16 + rsel;
                uint32_t q[4];
                ldm4(q, bh + (uint32_t)(r * SSTR) * 2 + koff);
                bhf[ib * 2 + 0][0] = q[0]; bhf[ib * 2 + 0][1] = q[2];
                bhf[ib * 2 + 1][0] = q[1]; bhf[ib * 2 + 1][1] = q[3];
                ldm4(q, bl + (uint32_t)(r * SSTR) * 2 + koff);
                blf[ib * 2 + 0][0] = q[0]; blf[ib * 2 + 0][1] = q[2];
                blf[ib * 2 + 1][0] = q[1]; blf[ib * 2 + 1][1] = q[3];
            }
            // Ah*Bh and Ah*Bl
#pragma unroll
            for (int im = 0; im < 4; im++) {
#pragma unroll
                for (int jn = 0; jn < 4; jn++) mma_bf16(acc[im][jn], a[im], bhf[jn]);
#pragma unroll
                for (int jn = 0; jn < 4; jn++) mma_bf16(acc[im][jn], a[im], blf[jn]);
            }
            // Al*Bh (reuse a regs)
#pragma unroll
            for (int im = 0; im < 4; im++) {
                const int r = wm * 64 + im * 16 + rsel;
                ldm4(a[im], al + (uint32_t)(r * SSTR) * 2 + koff);
            }
#pragma unroll
            for (int im = 0; im < 4; im++)
#pragma unroll
                for (int jn = 0; jn < 4; jn++) mma_bf16(acc[im][jn], a[im], bhf[jn]);
        }
    };

    const int S = 8;   // K=256 / BK=32
    issue(0, 0);
    for (int s = 0; s < S; s++) {
        if (s + 1 < S) {
            issue(s + 1, (s + 1) & 1);
            cp_wait<1>();
        } else {
            cp_wait<0>();
        }
        __syncthreads();
        compute(s & 1);
        __syncthreads();
    }

    // Epilogue
    const int cbase = n0 + wn * 32 + (lane & 3) * 2;
#pragma unroll
    for (int im = 0; im < 4; im++) {
        const int rbase = m0 + wm * 64 + im * 16 + (lane >> 2);
#pragma unroll
        for (int half = 0; half < 2; half++) {
            const int row = rbase + half * 8;
#pragma unroll
            for (int jn = 0; jn < 4; jn++) {
                const int col = cbase + jn * 8;
                float v0 = acc[im][jn][half * 2 + 0] + bias[col];
                float v1 = acc[im][jn][half * 2 + 1] + bias[col + 1];
                if (EPI == 0) {
                    *(float2*)(C + (size_t)row * ldc + col) = make_float2(v0, v1);
                } else if (EPI == 1) {
                    v0 = 0.5f * v0 * (1.0f + erff(v0 * 0.7071067811865476f));
                    v1 = 0.5f * v1 * (1.0f + erff(v1 * 0.7071067811865476f));
                    __nv_bfloat16 h0, l0, h1, l1;
                    split_bf16(v0, h0, l0);
                    split_bf16(v1, h1, l1);
                    __nv_bfloat162 hp; hp.x = h0; hp.y = h1;
                    __nv_bfloat162 lp; lp.x = l0; lp.y = l1;
                    *(__nv_bfloat162*)(Ch + (size_t)row * ldc + col) = hp;
                    *(__nv_bfloat162*)(Cl + (size_t)row * ldc + col) = lp;
                } else {
                    float2 rv = *(const float2*)(res + (size_t)row * ldc + col);
                    *(float2*)(C + (size_t)row * ldc + col) = make_float2(v0 + rv.x, v1 + rv.y);
                }
            }
        }
    }
}

// ---------------------------------------------------------------------------
// Split fp32 -> bf16 hi/lo
// ---------------------------------------------------------------------------
__global__ __launch_bounds__(256) void split_kernel(
    const float* __restrict__ in, __nv_bfloat16* __restrict__ hi,
    __nv_bfloat16* __restrict__ lo, int n)
{
    int i = (blockIdx.x * 256 + threadIdx.x) * 4;
    if (i >= n) return;
    float4 v = *(const float4*)(in + i);
    __nv_bfloat16 h0, l0, h1, l1, h2, l2, h3, l3;
    split_bf16(v.x, h0, l0);
    split_bf16(v.y, h1, l1);
    split_bf16(v.z, h2, l2);
    split_bf16(v.w, h3, l3);
    __nv_bfloat162 hp0; hp0.x = h0; hp0.y = h1;
    __nv_bfloat162 hp1; hp1.x = h2; hp1.y = h3;
    __nv_bfloat162 lp0; lp0.x = l0; lp0.y = l1;
    __nv_bfloat162 lp1; lp1.x = l2; lp1.y = l3;
    *(__nv_bfloat162*)(hi + i)     = hp0;
    *(__nv_bfloat162*)(hi + i + 2) = hp1;
    *(__nv_bfloat162*)(lo + i)     = lp0;
    *(__nv_bfloat162*)(lo + i + 2) = lp1;
}

// Weight transpose + split: w [K,N] fp32 -> [N,K] bf16 hi/lo
__global__ __launch_bounds__(256) void wsplit_kernel(
    const float* __restrict__ w, __nv_bfloat16* __restrict__ hi,
    __nv_bfloat16* __restrict__ lo, int K, int N)
{
    int idx = blockIdx.x * 256 + threadIdx.x;
    if (idx >= K * N) return;
    int nn = idx / K;
    int kk = idx - nn * K;
    float v = w[(size_t)kk * N + nn];
    __nv_bfloat16 h, l;
    split_bf16(v, h, l);
    hi[idx] = h;
    lo[idx] = l;
}

// ---------------------------------------------------------------------------
// Attention stage (SIMT)
// ---------------------------------------------------------------------------
__global__ __launch_bounds__(256) void kv_partial_kernel(
    const float* __restrict__ kg, const float* __restrict__ kb,
    const float* __restrict__ vg, const float* __restrict__ vb)
{
    const int chunk = blockIdx.x;
    const int bh    = blockIdx.y;
    const int b = bh >> 3, h = bh & 7;
    const int t = threadIdx.x, w = t >> 5, lane = t & 31;

    const float gkl = kg[lane], bkl = kb[lane];
    const float gvl = vg[lane], bvl = vb[lane];

    float acc[32];
#pragma unroll
    for (int i = 0; i < 32; i++) acc[i] = 0.0f;

    const int nbase = chunk * (HW / KV_CH);
    for (int n = nbase + w; n < nbase + HW / KV_CH; n += 8) {
        const float* row = g_qkv + (size_t)(b * HW + n) * QKVN + h * 96;
        float kx = row[32 + lane];
        float vx = row[64 + lane];

        float s = kx;
#pragma unroll
        for (int off = 16; off > 0; off >>= 1) s += __shfl_xor_sync(0xffffffffu, s, off);
        float mu = s * (1.0f / 32.0f);
        float d  = kx - mu;
        float s2 = d * d;
#pragma unroll
        for (int off = 16; off > 0; off >>= 1) s2 += __shfl_xor_sync(0xffffffffu, s2, off);
        float kn = d * rsqrtf(s2 * (1.0f / 32.0f) + 1e-5f) * gkl + bkl;

        float sv = vx;
#pragma unroll
        for (int off = 16; off > 0; off >>= 1) sv += __shfl_xor_sync(0xffffffffu, sv, off);
        float muv = sv * (1.0f / 32.0f);
        float dv  = vx - muv;
        float sv2 = dv * dv;
#pragma unroll
        for (int off = 16; off > 0; off >>= 1) sv2 += __shfl_xor_sync(0xffffffffu, sv2, off);
        float vn = dv * rsqrtf(sv2 * (1.0f / 32.0f) + 1e-5f) * gvl + bvl;

#pragma unroll
        for (int i = 0; i < 32; i++)
            acc[i] += __shfl_sync(0xffffffffu, kn, i) * vn;
    }

    __shared__ float buf[8][32][32];
#pragma unroll
    for (int i = 0; i < 32; i++) buf[w][i][lane] = acc[i];
    __syncthreads();

    float* outp = g_kvp + ((size_t)bh * KV_CH + chunk) * (HC * HC);
    for (int idx = t; idx < HC * HC; idx += 256) {
        float s = 0.0f;
#pragma unroll
        for (int ww = 0; ww < 8; ww++) s += buf[ww][idx >> 5][idx & 31];
        outp[idx] = s * (1.0f / (float)HW);
    }
}

__global__ __launch_bounds__(256) void attn_out_kernel(const float* __restrict__ x)
{
    const int chunk = blockIdx.x;
    const int bh    = blockIdx.y;
    const int b = bh >> 3, h = bh & 7;
    const int t = threadIdx.x;

    __shared__ float kv[HC][HC];
    for (int idx = t; idx < HC * HC; idx += 256) {
        float s = 0.0f;
#pragma unroll
        for (int c = 0; c < KV_CH; c++)
            s += g_kvp[((size_t)bh * KV_CH + c) * (HC * HC) + idx];
        kv[idx >> 5][idx & 31] = s;
    }
    __syncthreads();

    const int n = chunk * 256 + t;
    const size_t rowg = (size_t)(b * HW + n);
    const float* q = g_qkv + rowg * QKVN + h * 96;

    float qv[32];
#pragma unroll
    for (int i = 0; i < 32; i += 4) {
        float4 v = *(const float4*)(q + i);
        qv[i] = v.x; qv[i + 1] = v.y; qv[i + 2] = v.z; qv[i + 3] = v.w;
    }

    float acc[32];
#pragma unroll
    for (int j = 0; j < 32; j++) acc[j] = 0.0f;
#pragma unroll
    for (int i = 0; i < 32; i++) {
        float qi = qv[i];
#pragma unroll
        for (int j = 0; j < 32; j++) acc[j] += qi * kv[i][j];
    }

    const float* xr = x + rowg * CDIM + h * HC;
    __nv_bfloat16* hr = g_reth + rowg * CDIM + h * HC;
    __nv_bfloat16* lr = g_retl + rowg * CDIM + h * HC;
#pragma unroll
    for (int j = 0; j < 32; j += 4) {
        float4 xv = *(const float4*)(xr + j);
        float v0 = acc[j]     + xv.x;
        float v1 = acc[j + 1] + xv.y;
        float v2 = acc[j + 2] + xv.z;
        float v3 = acc[j + 3] + xv.w;
        __nv_bfloat16 h0, l0, h1, l1, h2, l2, h3, l3;
        split_bf16(v0, h0, l0);
        split_bf16(v1, h1, l1);
        split_bf16(v2, h2, l2);
        split_bf16(v3, h3, l3);
        __nv_bfloat162 hp0; hp0.x = h0; hp0.y = h1;
        __nv_bfloat162 hp1; hp1.x = h2; hp1.y = h3;
        __nv_bfloat162 lp0; lp0.x = l0; lp0.y = l1;
        __nv_bfloat162 lp1; lp1.x = l2; lp1.y = l3;
        *(__nv_bfloat162*)(hr + j)     = hp0;
        *(__nv_bfloat162*)(hr + j + 2) = hp1;
        *(__nv_bfloat162*)(lr + j)     = lp0;
        *(__nv_bfloat162*)(lr + j + 2) = lp1;
    }
}

// ---------------------------------------------------------------------------
// Launch
// ---------------------------------------------------------------------------
extern "C" void kernel_launch(void* const* d_in, const int* in_sizes, int n_in,
                              void* d_out, int out_size)
{
    const float* x     = (const float*)d_in[0];
    const float* w_qkv = (const float*)d_in[1];
    const float* b_qkv = (const float*)d_in[2];
    const float* kln_g = (const float*)d_in[3];
    const float* kln_b = (const float*)d_in[4];
    const float* vln_g = (const float*)d_in[5];
    const float* vln_b = (const float*)d_in[6];
    const float* w1    = (const float*)d_in[7];
    const float* b1    = (const float*)d_in[8];
    const float* w2    = (const float*)d_in[9];
    const float* b2    = (const float*)d_in[10];
    float* out = (float*)d_out;

    void *p_qkv, *p_xh, *p_xl, *p_reth, *p_retl, *p_hidh, *p_hidl;
    void *p_wqh, *p_wql, *p_w1h, *p_w1l, *p_w2h, *p_w2l;
    cudaGetSymbolAddress(&p_qkv, g_qkv);
    cudaGetSymbolAddress(&p_xh, g_xh);
    cudaGetSymbolAddress(&p_xl, g_xl);
    cudaGetSymbolAddress(&p_reth, g_reth);
    cudaGetSymbolAddress(&p_retl, g_retl);
    cudaGetSymbolAddress(&p_hidh, g_hidh);
    cudaGetSymbolAddress(&p_hidl, g_hidl);
    cudaGetSymbolAddress(&p_wqh, g_wqh);
    cudaGetSymbolAddress(&p_wql, g_wql);
    cudaGetSymbolAddress(&p_w1h, g_w1h);
    cudaGetSymbolAddress(&p_w1l, g_w1l);
    cudaGetSymbolAddress(&p_w2h, g_w2h);
    cudaGetSymbolAddress(&p_w2l, g_w2l);

    static int s_attr_done = 0;
    if (!s_attr_done) {
        cudaFuncSetAttribute(tc_gemm<0>, cudaFuncAttributeMaxDynamicSharedMemorySize, SMEM_TOTAL);
        cudaFuncSetAttribute(tc_gemm<1>, cudaFuncAttributeMaxDynamicSharedMemorySize, SMEM_TOTAL);
        cudaFuncSetAttribute(tc_gemm<2>, cudaFuncAttributeMaxDynamicSharedMemorySize, SMEM_TOTAL);
        s_attr_done = 1;
    }

    const int nx = MROWS * CDIM;

    split_kernel<<<(nx / 4 + 255) / 256, 256>>>(
        x, (__nv_bfloat16*)p_xh, (__nv_bfloat16*)p_xl, nx);
    wsplit_kernel<<<(CDIM * QKVN + 255) / 256, 256>>>(
        w_qkv, (__nv_bfloat16*)p_wqh, (__nv_bfloat16*)p_wql, CDIM, QKVN);
    wsplit_kernel<<<(CDIM * CDIM + 255) / 256, 256>>>(
        w1, (__nv_bfloat16*)p_w1h, (__nv_bfloat16*)p_w1l, CDIM, CDIM);
    wsplit_kernel<<<(CDIM * CDIM + 255) / 256, 256>>>(
        w2, (__nv_bfloat16*)p_w2h, (__nv_bfloat16*)p_w2l, CDIM, CDIM);

    // 1) qkv = x @ w_qkv + b_qkv  [32768, 768] fp32
    tc_gemm<0><<<dim3(MROWS / 128, QKVN / 128), 256, SMEM_TOTAL>>>(
        (const __nv_bfloat16*)p_xh, (const __nv_bfloat16*)p_xl,
        (const __nv_bfloat16*)p_wqh, (const __nv_bfloat16*)p_wql,
        b_qkv, nullptr, (float*)p_qkv, nullptr, nullptr, QKVN);

    // 2) attention
    kv_partial_kernel<<<dim3(KV_CH, BDIM * NHEAD), 256>>>(kln_g, kln_b, vln_g, vln_b);
    attn_out_kernel<<<dim3(16, BDIM * NHEAD), 256>>>(x);

    // 3) hid = gelu(ret @ w1 + b1) -> bf16 split
    tc_gemm<1><<<dim3(MROWS / 128, CDIM / 128), 256, SMEM_TOTAL>>>(
        (const __nv_bfloat16*)p_reth, (const __nv_bfloat16*)p_retl,
        (const __nv_bfloat16*)p_w1h, (const __nv_bfloat16*)p_w1l,
        b1, nullptr, nullptr, (__nv_bfloat16*)p_hidh, (__nv_bfloat16*)p_hidl, CDIM);

    // 4) out = hid @ w2 + b2 + x
    tc_gemm<2><<<dim3(MROWS / 128, CDIM / 128), 256, SMEM_TOTAL>>>(
        (const __nv_bfloat16*)p_hidh, (const __nv_bfloat16*)p_hidl,
        (const __nv_bfloat16*)p_w2h, (const __nv_bfloat16*)p_w2l,
        b2, x, out, nullptr, nullptr, CDIM);
}

// round 5
// speedup vs baseline: 1.6153x; 1.0166x over previous
#include <cuda_runtime.h>
#include <cuda_bf16.h>
#include <math.h>
#include <stdint.h>

// Problem constants
#define BDIM   8
#define HW     4096
#define CDIM   256
#define NHEAD  8
#define HC     32
#define MROWS  (BDIM * HW)   // 32768
#define QKVN   768
#define KV_CH  8

// ---------------------------------------------------------------------------
// Scratch (device globals)
// ---------------------------------------------------------------------------
__device__ float          g_qkv[(size_t)MROWS * QKVN];
__device__ __nv_bfloat16  g_xh[(size_t)MROWS * CDIM];
__device__ __nv_bfloat16  g_xl[(size_t)MROWS * CDIM];
__device__ __nv_bfloat16  g_reth[(size_t)MROWS * CDIM];
__device__ __nv_bfloat16  g_retl[(size_t)MROWS * CDIM];
__device__ __nv_bfloat16  g_hidh[(size_t)MROWS * CDIM];
__device__ __nv_bfloat16  g_hidl[(size_t)MROWS * CDIM];
__device__ __nv_bfloat16  g_wqh[(size_t)QKVN * CDIM];    // [N,K]
__device__ __nv_bfloat16  g_wql[(size_t)QKVN * CDIM];
__device__ __nv_bfloat16  g_w1h[CDIM * CDIM];
__device__ __nv_bfloat16  g_w1l[CDIM * CDIM];
__device__ __nv_bfloat16  g_w2h[CDIM * CDIM];
__device__ __nv_bfloat16  g_w2l[CDIM * CDIM];
__device__ float          g_kvp[BDIM * NHEAD * KV_CH * HC * HC];

// ---------------------------------------------------------------------------
// PTX helpers (sm_80-era: valid under compute_103)
// ---------------------------------------------------------------------------
__device__ __forceinline__ uint32_t smem_u32(const void* p) {
    uint32_t a;
    asm("{ .reg .u64 t; cvta.to.shared.u64 t, %1; cvt.u32.u64 %0, t; }"
        : "=r"(a) : "l"(p));
    return a;
}

__device__ __forceinline__ void cp_async16(uint32_t dst, const void* src) {
    asm volatile("cp.async.cg.shared.global [%0], [%1], 16;"
                 :: "r"(dst), "l"(src) : "memory");
}
__device__ __forceinline__ void cp_commit() {
    asm volatile("cp.async.commit_group;" ::: "memory");
}
template <int N>
__device__ __forceinline__ void cp_wait() {
    asm volatile("cp.async.wait_group %0;" :: "n"(N) : "memory");
}

__device__ __forceinline__ void ldm4(uint32_t* r, uint32_t addr) {
    asm volatile("ldmatrix.sync.aligned.m8n8.x4.shared.b16 {%0,%1,%2,%3}, [%4];"
                 : "=r"(r[0]), "=r"(r[1]), "=r"(r[2]), "=r"(r[3]) : "r"(addr));
}

__device__ __forceinline__ void mma_bf16(float* d, const uint32_t* a, const uint32_t* b) {
    asm volatile(
        "mma.sync.aligned.m16n8k16.row.col.f32.bf16.bf16.f32 "
        "{%0,%1,%2,%3}, {%4,%5,%6,%7}, {%8,%9}, {%0,%1,%2,%3};"
        : "+f"(d[0]), "+f"(d[1]), "+f"(d[2]), "+f"(d[3])
        : "r"(a[0]), "r"(a[1]), "r"(a[2]), "r"(a[3]), "r"(b[0]), "r"(b[1]));
}

__device__ __forceinline__ void split_bf16(float v, __nv_bfloat16& h, __nv_bfloat16& l) {
    h = __float2bfloat16(v);
    l = __float2bfloat16(v - __bfloat162float(h));
}

// ---------------------------------------------------------------------------
// Merged-pass split GEMM via mma.sync, dependency-aware MMA ordering.
//   C[M,N] = A[M,256] @ B[N,256]^T, D = Ah*Bh + Ah*Bl + Al*Bh, fp32 accum.
// Tile 128x128, 256 threads, warp grid 2(m) x 4(n), warp tile 64x32, BK=32.
// Dynamic smem: 4 tiles x 2 buffers x 10240B = 80 KB.
// ---------------------------------------------------------------------------
#define SSTR 40                   // smem row stride in bf16 elems (80B)
#define TILEBYT (128 * SSTR * 2)  // 10240 bytes
#define SMEM_TOTAL (TILEBYT * 8)  // 81920

template <int EPI>
__global__ __launch_bounds__(256, 2) void tc_gemm(
    const __nv_bfloat16* __restrict__ Ah, const __nv_bfloat16* __restrict__ Al,
    const __nv_bfloat16* __restrict__ Bh, const __nv_bfloat16* __restrict__ Bl,
    const float* __restrict__ bias, const float* __restrict__ res,
    float* __restrict__ C,
    __nv_bfloat16* __restrict__ Ch, __nv_bfloat16* __restrict__ Cl,
    int ldc)
{
    extern __shared__ __align__(128) unsigned char smraw[];

    const int t    = threadIdx.x;
    const int lane = t & 31;
    const int wid  = t >> 5;
    const int wm   = wid & 1;      // 0..1
    const int wn   = wid >> 1;     // 0..3
    const int m0   = blockIdx.x * 128;
    const int n0   = blockIdx.y * 128;

    const uint32_t sb = smem_u32(smraw);

    // global->smem mapping: 4 threads per 64B row, 2 rows per thread per tile
    const int lrow = t >> 2;         // 0..63
    const int lcol = (t & 3) * 8;    // elem offset (16B chunks)

    float acc[4][4][4];
#pragma unroll
    for (int i = 0; i < 4; i++)
#pragma unroll
        for (int j = 0; j < 4; j++)
#pragma unroll
            for (int q = 0; q < 4; q++) acc[i][j][q] = 0.0f;

    const __nv_bfloat16* tsrc[4] = {Ah, Al, Bh, Bl};
    const int tbase[4] = {m0, m0, n0, n0};

    auto issue = [&](int s, int buf) {
        const int k0 = s * 32;
#pragma unroll
        for (int tile = 0; tile < 4; tile++) {
            const __nv_bfloat16* src = tsrc[tile] + (size_t)(tbase[tile] + lrow) * CDIM + k0 + lcol;
            const uint32_t dbase = sb + (uint32_t)(buf * 4 + tile) * TILEBYT
                                 + (uint32_t)(lrow * SSTR + lcol) * 2;
            cp_async16(dbase, src);
            cp_async16(dbase + 64 * SSTR * 2, src + (size_t)64 * CDIM);
        }
        cp_commit();
    };

    // Per-warp ldmatrix base offsets (within a tile)
    const int rsel  = lane & 15;
    const int khalf = (lane >> 4) * 8;
    const uint32_t aoff = (uint32_t)((wm * 64 + rsel) * SSTR + khalf) * 2;
    const uint32_t boff = (uint32_t)((wn * 32 + rsel) * SSTR + khalf) * 2;

    auto compute = [&](int buf) {
        const uint32_t ah = sb + (uint32_t)(buf * 4 + 0) * TILEBYT + aoff;
        const uint32_t al = sb + (uint32_t)(buf * 4 + 1) * TILEBYT + aoff;
        const uint32_t bh = sb + (uint32_t)(buf * 4 + 2) * TILEBYT + boff;
        const uint32_t bl = sb + (uint32_t)(buf * 4 + 3) * TILEBYT + boff;
#pragma unroll
        for (int ks = 0; ks < 2; ks++) {
            const uint32_t koff = (uint32_t)(ks * 16) * 2;

            uint32_t a[4][4];
#pragma unroll
            for (int im = 0; im < 4; im++)
                ldm4(a[im], ah + (uint32_t)(im * 16 * SSTR) * 2 + koff);

            uint32_t bhf[4][2], blf[4][2];
#pragma unroll
            for (int ib = 0; ib < 2; ib++) {
                uint32_t q[4];
                ldm4(q, bh + (uint32_t)(ib * 16 * SSTR) * 2 + koff);
                bhf[ib * 2 + 0][0] = q[0]; bhf[ib * 2 + 0][1] = q[2];
                bhf[ib * 2 + 1][0] = q[1]; bhf[ib * 2 + 1][1] = q[3];
                ldm4(q, bl + (uint32_t)(ib * 16 * SSTR) * 2 + koff);
                blf[ib * 2 + 0][0] = q[0]; blf[ib * 2 + 0][1] = q[2];
                blf[ib * 2 + 1][0] = q[1]; blf[ib * 2 + 1][1] = q[3];
            }

            // Group-major: 16 independent accumulators between any reuse
#pragma unroll
            for (int im = 0; im < 4; im++)
#pragma unroll
                for (int jn = 0; jn < 4; jn++) mma_bf16(acc[im][jn], a[im], bhf[jn]);
#pragma unroll
            for (int im = 0; im < 4; im++)
#pragma unroll
                for (int jn = 0; jn < 4; jn++) mma_bf16(acc[im][jn], a[im], blf[jn]);
            // overwrite a with Al (WAR only; scoreboard-safe)
#pragma unroll
            for (int im = 0; im < 4; im++)
                ldm4(a[im], al + (uint32_t)(im * 16 * SSTR) * 2 + koff);
#pragma unroll
            for (int im = 0; im < 4; im++)
#pragma unroll
                for (int jn = 0; jn < 4; jn++) mma_bf16(acc[im][jn], a[im], bhf[jn]);
        }
    };

    issue(0, 0);
#pragma unroll
    for (int s = 0; s < 8; s++) {
        if (s + 1 < 8) {
            issue(s + 1, (s + 1) & 1);
            cp_wait<1>();
        } else {
            cp_wait<0>();
        }
        __syncthreads();
        compute(s & 1);
        __syncthreads();
    }

    // Epilogue
    const int cbase = n0 + wn * 32 + (lane & 3) * 2;
#pragma unroll
    for (int im = 0; im < 4; im++) {
        const int rbase = m0 + wm * 64 + im * 16 + (lane >> 2);
#pragma unroll
        for (int half = 0; half < 2; half++) {
            const int row = rbase + half * 8;
#pragma unroll
            for (int jn = 0; jn < 4; jn++) {
                const int col = cbase + jn * 8;
                float v0 = acc[im][jn][half * 2 + 0] + bias[col];
                float v1 = acc[im][jn][half * 2 + 1] + bias[col + 1];
                if (EPI == 0) {
                    *(float2*)(C + (size_t)row * ldc + col) = make_float2(v0, v1);
                } else if (EPI == 1) {
                    v0 = 0.5f * v0 * (1.0f + erff(v0 * 0.7071067811865476f));
                    v1 = 0.5f * v1 * (1.0f + erff(v1 * 0.7071067811865476f));
                    __nv_bfloat16 h0, l0, h1, l1;
                    split_bf16(v0, h0, l0);
                    split_bf16(v1, h1, l1);
                    __nv_bfloat162 hp; hp.x = h0; hp.y = h1;
                    __nv_bfloat162 lp; lp.x = l0; lp.y = l1;
                    *(__nv_bfloat162*)(Ch + (size_t)row * ldc + col) = hp;
                    *(__nv_bfloat162*)(Cl + (size_t)row * ldc + col) = lp;
                } else {
                    float2 rv = *(const float2*)(res + (size_t)row * ldc + col);
                    *(float2*)(C + (size_t)row * ldc + col) = make_float2(v0 + rv.x, v1 + rv.y);
                }
            }
        }
    }
}

// ---------------------------------------------------------------------------
// Split fp32 -> bf16 hi/lo
// ---------------------------------------------------------------------------
__global__ __launch_bounds__(256) void split_kernel(
    const float* __restrict__ in, __nv_bfloat16* __restrict__ hi,
    __nv_bfloat16* __restrict__ lo, int n)
{
    int i = (blockIdx.x * 256 + threadIdx.x) * 4;
    if (i >= n) return;
    float4 v = *(const float4*)(in + i);
    __nv_bfloat16 h0, l0, h1, l1, h2, l2, h3, l3;
    split_bf16(v.x, h0, l0);
    split_bf16(v.y, h1, l1);
    split_bf16(v.z, h2, l2);
    split_bf16(v.w, h3, l3);
    __nv_bfloat162 hp0; hp0.x = h0; hp0.y = h1;
    __nv_bfloat162 hp1; hp1.x = h2; hp1.y = h3;
    __nv_bfloat162 lp0; lp0.x = l0; lp0.y = l1;
    __nv_bfloat162 lp1; lp1.x = l2; lp1.y = l3;
    *(__nv_bfloat162*)(hi + i)     = hp0;
    *(__nv_bfloat162*)(hi + i + 2) = hp1;
    *(__nv_bfloat162*)(lo + i)     = lp0;
    *(__nv_bfloat162*)(lo + i + 2) = lp1;
}

// Weight transpose + split: w [K,N] fp32 -> [N,K] bf16 hi/lo
__global__ __launch_bounds__(256) void wsplit_kernel(
    const float* __restrict__ w, __nv_bfloat16* __restrict__ hi,
    __nv_bfloat16* __restrict__ lo, int K, int N)
{
    int idx = blockIdx.x * 256 + threadIdx.x;
    if (idx >= K * N) return;
    int nn = idx / K;
    int kk = idx - nn * K;
    float v = w[(size_t)kk * N + nn];
    __nv_bfloat16 h, l;
    split_bf16(v, h, l);
    hi[idx] = h;
    lo[idx] = l;
}

// ---------------------------------------------------------------------------
// Attention stage (SIMT)
// ---------------------------------------------------------------------------
__global__ __launch_bounds__(256) void kv_partial_kernel(
    const float* __restrict__ kg, const float* __restrict__ kb,
    const float* __restrict__ vg, const float* __restrict__ vb)
{
    const int chunk = blockIdx.x;
    const int bh    = blockIdx.y;
    const int b = bh >> 3, h = bh & 7;
    const int t = threadIdx.x, w = t >> 5, lane = t & 31;

    const float gkl = kg[lane], bkl = kb[lane];
    const float gvl = vg[lane], bvl = vb[lane];

    float acc[32];
#pragma unroll
    for (int i = 0; i < 32; i++) acc[i] = 0.0f;

    const int nbase = chunk * (HW / KV_CH);
    for (int n = nbase + w; n < nbase + HW / KV_CH; n += 8) {
        const float* row = g_qkv + (size_t)(b * HW + n) * QKVN + h * 96;
        float kx = row[32 + lane];
        float vx = row[64 + lane];

        float s = kx;
#pragma unroll
        for (int off = 16; off > 0; off >>= 1) s += __shfl_xor_sync(0xffffffffu, s, off);
        float mu = s * (1.0f / 32.0f);
        float d  = kx - mu;
        float s2 = d * d;
#pragma unroll
        for (int off = 16; off > 0; off >>= 1) s2 += __shfl_xor_sync(0xffffffffu, s2, off);
        float kn = d * rsqrtf(s2 * (1.0f / 32.0f) + 1e-5f) * gkl + bkl;

        float sv = vx;
#pragma unroll
        for (int off = 16; off > 0; off >>= 1) sv += __shfl_xor_sync(0xffffffffu, sv, off);
        float muv = sv * (1.0f / 32.0f);
        float dv  = vx - muv;
        float sv2 = dv * dv;
#pragma unroll
        for (int off = 16; off > 0; off >>= 1) sv2 += __shfl_xor_sync(0xffffffffu, sv2, off);
        float vn = dv * rsqrtf(sv2 * (1.0f / 32.0f) + 1e-5f) * gvl + bvl;

#pragma unroll
        for (int i = 0; i < 32; i++)
            acc[i] += __shfl_sync(0xffffffffu, kn, i) * vn;
    }

    __shared__ float buf[8][32][32];
#pragma unroll
    for (int i = 0; i < 32; i++) buf[w][i][lane] = acc[i];
    __syncthreads();

    float* outp = g_kvp + ((size_t)bh * KV_CH + chunk) * (HC * HC);
    for (int idx = t; idx < HC * HC; idx += 256) {
        float s = 0.0f;
#pragma unroll
        for (int ww = 0; ww < 8; ww++) s += buf[ww][idx >> 5][idx & 31];
        outp[idx] = s * (1.0f / (float)HW);
    }
}

__global__ __launch_bounds__(256) void attn_out_kernel(const float* __restrict__ x)
{
    const int chunk = blockIdx.x;
    const int bh    = blockIdx.y;
    const int b = bh >> 3, h = bh & 7;
    const int t = threadIdx.x;

    __shared__ float kv[HC][HC];
    for (int idx = t; idx < HC * HC; idx += 256) {
        float s = 0.0f;
#pragma unroll
        for (int c = 0; c < KV_CH; c++)
            s += g_kvp[((size_t)bh * KV_CH + c) * (HC * HC) + idx];
        kv[idx >> 5][idx & 31] = s;
    }
    __syncthreads();

    const int n = chunk * 256 + t;
    const size_t rowg = (size_t)(b * HW + n);
    const float* q = g_qkv + rowg * QKVN + h * 96;

    float qv[32];
#pragma unroll
    for (int i = 0; i < 32; i += 4) {
        float4 v = *(const float4*)(q + i);
        qv[i] = v.x; qv[i + 1] = v.y; qv[i + 2] = v.z; qv[i + 3] = v.w;
    }

    float acc[32];
#pragma unroll
    for (int j = 0; j < 32; j++) acc[j] = 0.0f;
#pragma unroll
    for (int i = 0; i < 32; i++) {
        float qi = qv[i];
#pragma unroll
        for (int j = 0; j < 32; j++) acc[j] += qi * kv[i][j];
    }

    const float* xr = x + rowg * CDIM + h * HC;
    __nv_bfloat16* hr = g_reth + rowg * CDIM + h * HC;
    __nv_bfloat16* lr = g_retl + rowg * CDIM + h * HC;
#pragma unroll
    for (int j = 0; j < 32; j += 4) {
        float4 xv = *(const float4*)(xr + j);
        float v0 = acc[j]     + xv.x;
        float v1 = acc[j + 1] + xv.y;
        float v2 = acc[j + 2] + xv.z;
        float v3 = acc[j + 3] + xv.w;
        __nv_bfloat16 h0, l0, h1, l1, h2, l2, h3, l3;
        split_bf16(v0, h0, l0);
        split_bf16(v1, h1, l1);
        split_bf16(v2, h2, l2);
        split_bf16(v3, h3, l3);
        __nv_bfloat162 hp0; hp0.x = h0; hp0.y = h1;
        __nv_bfloat162 hp1; hp1.x = h2; hp1.y = h3;
        __nv_bfloat162 lp0; lp0.x = l0; lp0.y = l1;
        __nv_bfloat162 lp1; lp1.x = l2; lp1.y = l3;
        *(__nv_bfloat162*)(hr + j)     = hp0;
        *(__nv_bfloat162*)(hr + j + 2) = hp1;
        *(__nv_bfloat162*)(lr + j)     = lp0;
        *(__nv_bfloat162*)(lr + j + 2) = lp1;
    }
}

// ---------------------------------------------------------------------------
// Launch
// ---------------------------------------------------------------------------
extern "C" void kernel_launch(void* const* d_in, const int* in_sizes, int n_in,
                              void* d_out, int out_size)
{
    const float* x     = (const float*)d_in[0];
    const float* w_qkv = (const float*)d_in[1];
    const float* b_qkv = (const float*)d_in[2];
    const float* kln_g = (const float*)d_in[3];
    const float* kln_b = (const float*)d_in[4];
    const float* vln_g = (const float*)d_in[5];
    const float* vln_b = (const float*)d_in[6];
    const float* w1    = (const float*)d_in[7];
    const float* b1    = (const float*)d_in[8];
    const float* w2    = (const float*)d_in[9];
    const float* b2    = (const float*)d_in[10];
    float* out = (float*)d_out;

    void *p_qkv, *p_xh, *p_xl, *p_reth, *p_retl, *p_hidh, *p_hidl;
    void *p_wqh, *p_wql, *p_w1h, *p_w1l, *p_w2h, *p_w2l;
    cudaGetSymbolAddress(&p_qkv, g_qkv);
    cudaGetSymbolAddress(&p_xh, g_xh);
    cudaGetSymbolAddress(&p_xl, g_xl);
    cudaGetSymbolAddress(&p_reth, g_reth);
    cudaGetSymbolAddress(&p_retl, g_retl);
    cudaGetSymbolAddress(&p_hidh, g_hidh);
    cudaGetSymbolAddress(&p_hidl, g_hidl);
    cudaGetSymbolAddress(&p_wqh, g_wqh);
    cudaGetSymbolAddress(&p_wql, g_wql);
    cudaGetSymbolAddress(&p_w1h, g_w1h);
    cudaGetSymbolAddress(&p_w1l, g_w1l);
    cudaGetSymbolAddress(&p_w2h, g_w2h);
    cudaGetSymbolAddress(&p_w2l, g_w2l);

    static int s_attr_done = 0;
    if (!s_attr_done) {
        cudaFuncSetAttribute(tc_gemm<0>, cudaFuncAttributeMaxDynamicSharedMemorySize, SMEM_TOTAL);
        cudaFuncSetAttribute(tc_gemm<1>, cudaFuncAttributeMaxDynamicSharedMemorySize, SMEM_TOTAL);
        cudaFuncSetAttribute(tc_gemm<2>, cudaFuncAttributeMaxDynamicSharedMemorySize, SMEM_TOTAL);
        s_attr_done = 1;
    }

    const int nx = MROWS * CDIM;

    split_kernel<<<(nx / 4 + 255) / 256, 256>>>(
        x, (__nv_bfloat16*)p_xh, (__nv_bfloat16*)p_xl, nx);
    wsplit_kernel<<<(CDIM * QKVN + 255) / 256, 256>>>(
        w_qkv, (__nv_bfloat16*)p_wqh, (__nv_bfloat16*)p_wql, CDIM, QKVN);
    wsplit_kernel<<<(CDIM * CDIM + 255) / 256, 256>>>(
        w1, (__nv_bfloat16*)p_w1h, (__nv_bfloat16*)p_w1l, CDIM, CDIM);
    wsplit_kernel<<<(CDIM * CDIM + 255) / 256, 256>>>(
        w2, (__nv_bfloat16*)p_w2h, (__nv_bfloat16*)p_w2l, CDIM, CDIM);

    // 1) qkv = x @ w_qkv + b_qkv  [32768, 768] fp32
    tc_gemm<0><<<dim3(MROWS / 128, QKVN / 128), 256, SMEM_TOTAL>>>(
        (const __nv_bfloat16*)p_xh, (const __nv_bfloat16*)p_xl,
        (const __nv_bfloat16*)p_wqh, (const __nv_bfloat16*)p_wql,
        b_qkv, nullptr, (float*)p_qkv, nullptr, nullptr, QKVN);

    // 2) attention
    kv_partial_kernel<<<dim3(KV_CH, BDIM * NHEAD), 256>>>(kln_g, kln_b, vln_g, vln_b);
    attn_out_kernel<<<dim3(16, BDIM * NHEAD), 256>>>(x);

    // 3) hid = gelu(ret @ w1 + b1) -> bf16 split
    tc_gemm<1><<<dim3(MROWS / 128, CDIM / 128), 256, SMEM_TOTAL>>>(
        (const __nv_bfloat16*)p_reth, (const __nv_bfloat16*)p_retl,
        (const __nv_bfloat16*)p_w1h, (const __nv_bfloat16*)p_w1l,
        b1, nullptr, nullptr, (__nv_bfloat16*)p_hidh, (__nv_bfloat16*)p_hidl, CDIM);

    // 4) out = hid @ w2 + b2 + x
    tc_gemm<2><<<dim3(MROWS / 128, CDIM / 128), 256, SMEM_TOTAL>>>(
        (const __nv_bfloat16*)p_hidh, (const __nv_bfloat16*)p_hidl,
        (const __nv_bfloat16*)p_w2h, (const __nv_bfloat16*)p_w2l,
        b2, x, out, nullptr, nullptr, CDIM);
}